// round 11
// baseline (speedup 1.0000x reference)
#include <cuda_runtime.h>
#include <cuda_bf16.h>
#include <mma.h>
#include <cstdint>

using namespace nvcuda;

#define NN 50000
#define EE 800000
#define DD 128
#define FFD 512

// ---------------- scratch (static device globals; no allocs allowed) -------------
__device__ __align__(16) float g_h  [NN * DD];   // h = x @ W
__device__ __align__(16) float g_acc[NN * DD];   // unnormalized aggregation
__device__ __align__(16) float g_v1 [NN * DD];   // LN1 output (residual for LN2)
__device__ __align__(16) float g_t  [NN * FFD];  // relu(v1@W1+b1), fp32
__device__ float g_asrc[NN];
__device__ float g_adst[NN];
__device__ float g_denom[NN];
__device__ int   g_idx32;   // 1 if edge_index is int32, 0 if int64

// weights, transposed to [N,K] K-major, bf16 hi/lo split
__device__ __align__(16) __nv_bfloat16 g_wt0h[DD * DD];
__device__ __align__(16) __nv_bfloat16 g_wt0l[DD * DD];
__device__ __align__(16) __nv_bfloat16 g_wt1h[FFD * DD];
__device__ __align__(16) __nv_bfloat16 g_wt1l[FFD * DD];
__device__ __align__(16) __nv_bfloat16 g_wt2h[DD * FFD];
__device__ __align__(16) __nv_bfloat16 g_wt2l[DD * FFD];

// ---------------- small helpers ----------------
__device__ __forceinline__ uint32_t smem_u32(const void* p) {
    uint32_t a;
    asm("{ .reg .u64 t; cvta.to.shared.u64 t, %1; cvt.u32.u64 %0, t; }" : "=r"(a) : "l"(p));
    return a;
}

__device__ __forceinline__ void cp_async16(uint32_t saddr, const void* gaddr) {
    asm volatile("cp.async.cg.shared.global [%0], [%1], 16;" :: "r"(saddr), "l"(gaddr));
}
#define CP_COMMIT() asm volatile("cp.async.commit_group;" ::: "memory")
#define CP_WAIT0()  asm volatile("cp.async.wait_group 0;" ::: "memory")

__device__ __forceinline__ void load_edge(const void* ei, int e, int E, int& s, int& d) {
    if (g_idx32) {
        const int* p = (const int*)ei;
        s = p[e]; d = p[E + e];
    } else {
        const long long* p = (const long long*)ei;
        s = (int)p[e]; d = (int)p[(size_t)E + e];
    }
}

__device__ __forceinline__ void red_add_v4(float* addr, float4 v) {
    asm volatile("red.global.add.v4.f32 [%0], {%1,%2,%3,%4};"
                 :: "l"(addr), "f"(v.x), "f"(v.y), "f"(v.z), "f"(v.w) : "memory");
}

__device__ __forceinline__ float warp_sum(float v) {
    #pragma unroll
    for (int o = 16; o > 0; o >>= 1) v += __shfl_xor_sync(0xffffffffu, v, o);
    return v;
}

__device__ __forceinline__ void split1(float v, __nv_bfloat16& h, __nv_bfloat16& l) {
    h = __float2bfloat16(v);
    l = __float2bfloat16(v - __bfloat162float(h));
}

// ---------------- prep A: W, W1 transpose+split + idx32 reset -------------------
__global__ void k_prep_a(const float* __restrict__ W, const float* __restrict__ W1) {
    int idx = blockIdx.x * blockDim.x + threadIdx.x;
    if (idx == 0) g_idx32 = 0;
    __nv_bfloat16 h, l;
    if (idx < DD * DD) {
        int k = idx / DD, n = idx % DD;
        split1(W[idx], h, l);
        g_wt0h[n * DD + k] = h;
        g_wt0l[n * DD + k] = l;
    } else if (idx < DD * DD + DD * FFD) {
        int i = idx - DD * DD;
        int k = i / FFD, n = i % FFD;
        split1(W1[i], h, l);
        g_wt1h[n * DD + k] = h;
        g_wt1l[n * DD + k] = l;
    }
}

// ---------------- prep B: W2 transpose+split ------------------------------------
__global__ void k_prep_b(const float* __restrict__ W2) {
    int idx = blockIdx.x * blockDim.x + threadIdx.x;
    if (idx < FFD * DD) {
        int k = idx / DD, n = idx % DD;
        __nv_bfloat16 h, l;
        split1(W2[idx], h, l);
        g_wt2h[n * FFD + k] = h;
        g_wt2l[n * FFD + k] = l;
    }
}

// ---------------- dtype detection ----------------
__global__ void k_detect(const unsigned int* w, int E) {
    int any = 0;
    for (int i = blockIdx.x * blockDim.x + threadIdx.x; i < E; i += gridDim.x * blockDim.x)
        if (w[2 * i + 1] != 0u) any = 1;
    if (any) g_idx32 = 1;
}

// ---------------- wmma (HMMA) bf16-split GEMM, 512 threads / 16 warps ------------
// C[M,Nn] = A[M,K] @ Bt[Nn,K]^T with 3-term hi/lo compensation.
// CTA tile 128x128, 16 warps as 4x4, warp tile 32x32 (acc[2][2]).
// SLDA=40 bf16 (80B row stride): ldmatrix row addresses hit banks r*20 mod 32 =
// {0,20,8,28,16,4,24,12} -> conflict-free (SLDA=48/96B gave 2-way conflicts).
// mode 1: Cf = relu(r + bias)
// mode 3: h-row out + fused node init (attention coefs + self loop)
// mode 4: Cf = LN(r + bias + resid; q1=gamma, q2=beta)
#define SLDA 40
#define CLD  132
#define AH_OFF 0
#define AL_OFF (128 * SLDA * 2)              // 10240
#define BH_OFF (2 * 128 * SLDA * 2)          // 20480
#define BL_OFF (3 * 128 * SLDA * 2)          // 30720
#define STAGE  (4 * 128 * SLDA * 2)          // 40960
#define WG_SMEM (2 * STAGE)                  // 81920 (>= 128*CLD*4 = 67584 for C stage)

__global__ void __launch_bounds__(512)
k_wgemm(const float* __restrict__ Af,
        const __nv_bfloat16* __restrict__ Bh, const __nv_bfloat16* __restrict__ Bl,
        float* __restrict__ Cf,
        const float* __restrict__ bias, const float* __restrict__ resid,
        const float* __restrict__ q1, const float* __restrict__ q2,
        int M, int K, int Nn, int mode) {
    extern __shared__ char smem[];
    const int tid = threadIdx.x;
    const int wid = tid >> 5;
    const int lane = tid & 31;
    const int warp_m = wid & 3;          // 4 m-groups of 32 rows
    const int warp_n = wid >> 2;         // 4 n-groups of 32 cols
    const int row0 = blockIdx.x * 128;
    const int col0 = blockIdx.y * 128;
    uint32_t sbase = smem_u32(smem);

    // fill coords: 512 threads cover 128 rows x 4 chunks (8 elems each) exactly
    const int fr = tid >> 2, fq = tid & 3;
    int ga = row0 + fr; if (ga > M - 1) ga = M - 1;

    wmma::fragment<wmma::accumulator, 16, 16, 16, float> acc[2][2];
    #pragma unroll
    for (int i = 0; i < 2; i++)
        #pragma unroll
        for (int j = 0; j < 2; j++) wmma::fill_fragment(acc[i][j], 0.f);

    float4 pa[2];

    #define FILL_B(kk, stg) do {                                              \
        uint32_t so = sbase + (stg) * STAGE + BH_OFF + fr * (SLDA*2) + fq*16;  \
        size_t bo = (size_t)(col0 + fr) * K + (kk) + fq * 8;                  \
        cp_async16(so, Bh + bo);                                              \
        cp_async16(so + (BL_OFF - BH_OFF), Bl + bo);                          \
        CP_COMMIT();                                                          \
    } while (0)

    #define LOAD_A(kk) do {                                                   \
        const float* p = Af + (size_t)ga * K + (kk) + fq * 8;                 \
        pa[0] = *(const float4*)p; pa[1] = *(const float4*)(p + 4);           \
    } while (0)

    #define STORE_A(stg) do {                                                 \
        float f[8] = {pa[0].x, pa[0].y, pa[0].z, pa[0].w,                     \
                      pa[1].x, pa[1].y, pa[1].z, pa[1].w};                    \
        __nv_bfloat162 vh[4], vl[4];                                          \
        _Pragma("unroll")                                                     \
        for (int j = 0; j < 4; j++) {                                         \
            __nv_bfloat16 h0, l0, h1, l1;                                     \
            split1(f[2*j], h0, l0); split1(f[2*j+1], h1, l1);                 \
            vh[j] = __nv_bfloat162(h0, h1); vl[j] = __nv_bfloat162(l0, l1);   \
        }                                                                     \
        char* ba = smem + (stg) * STAGE + fr * (SLDA*2) + fq * 16;            \
        *(uint4*)(ba + AH_OFF) = *(uint4*)vh;                                 \
        *(uint4*)(ba + AL_OFF) = *(uint4*)vl;                                 \
    } while (0)

    LOAD_A(0);
    FILL_B(0, 0);
    STORE_A(0);
    CP_WAIT0();
    __syncthreads();

    int stg = 0;
    for (int kk = 0; kk < K; kk += 32) {
        bool more = (kk + 32 < K);
        if (more) {
            FILL_B(kk + 32, stg ^ 1);
            LOAD_A(kk + 32);
        }

        const __nv_bfloat16* sAh = (const __nv_bfloat16*)(smem + stg * STAGE + AH_OFF);
        const __nv_bfloat16* sBh = (const __nv_bfloat16*)(smem + stg * STAGE + BH_OFF);

        #pragma unroll
        for (int ks = 0; ks < 32; ks += 16) {
            wmma::fragment<wmma::matrix_a, 16, 16, 16, __nv_bfloat16, wmma::row_major> ah[2], al[2];
            wmma::fragment<wmma::matrix_b, 16, 16, 16, __nv_bfloat16, wmma::col_major> bh[2], bl[2];
            #pragma unroll
            for (int i = 0; i < 2; i++) {
                const __nv_bfloat16* pA = sAh + (warp_m * 32 + i * 16) * SLDA + ks;
                wmma::load_matrix_sync(ah[i], pA, SLDA);
                wmma::load_matrix_sync(al[i], pA + (AL_OFF - AH_OFF) / 2, SLDA);
            }
            #pragma unroll
            for (int j = 0; j < 2; j++) {
                const __nv_bfloat16* pB = sBh + (warp_n * 32 + j * 16) * SLDA + ks;
                wmma::load_matrix_sync(bh[j], pB, SLDA);
                wmma::load_matrix_sync(bl[j], pB + (BL_OFF - BH_OFF) / 2, SLDA);
            }
            // term-outer issue order: consecutive MMAs hit different accumulators
            #pragma unroll
            for (int i = 0; i < 2; i++)
                #pragma unroll
                for (int j = 0; j < 2; j++)
                    wmma::mma_sync(acc[i][j], ah[i], bh[j], acc[i][j]);
            #pragma unroll
            for (int i = 0; i < 2; i++)
                #pragma unroll
                for (int j = 0; j < 2; j++)
                    wmma::mma_sync(acc[i][j], ah[i], bl[j], acc[i][j]);
            #pragma unroll
            for (int i = 0; i < 2; i++)
                #pragma unroll
                for (int j = 0; j < 2; j++)
                    wmma::mma_sync(acc[i][j], al[i], bh[j], acc[i][j]);
        }

        if (more) {
            STORE_A(stg ^ 1);
            CP_WAIT0();
        }
        __syncthreads();
        stg ^= 1;
    }

    // stage C tile in smem
    float* sC = (float*)smem;
    #pragma unroll
    for (int i = 0; i < 2; i++)
        #pragma unroll
        for (int j = 0; j < 2; j++)
            wmma::store_matrix_sync(sC + (warp_m * 32 + i * 16) * CLD + warp_n * 32 + j * 16,
                                    acc[i][j], CLD, wmma::mem_row_major);
    __syncthreads();

    if (mode == 1) {
        #pragma unroll
        for (int it = 0; it < 8; it++) {
            int i = tid + it * 512;
            int rr = i >> 5, q = i & 31;
            int gr = row0 + rr;
            if (gr >= M) continue;
            int gc = col0 + q * 4;
            float4 v = *(const float4*)(sC + rr * CLD + q * 4);
            const float4 bb = *(const float4*)(bias + gc);
            v.x = fmaxf(v.x + bb.x, 0.f); v.y = fmaxf(v.y + bb.y, 0.f);
            v.z = fmaxf(v.z + bb.z, 0.f); v.w = fmaxf(v.w + bb.w, 0.f);
            *(float4*)(Cf + (size_t)gr * Nn + gc) = v;
        }
    } else if (mode == 3) {
        // h rows + fused node init: warp per row, 8 rows per warp
        float4 as = ((const float4*)q1)[lane];
        float4 ad = ((const float4*)q2)[lane];
        #pragma unroll
        for (int rr = 0; rr < 8; rr++) {
            int r = wid * 8 + rr;
            int gr = row0 + r;
            if (gr >= M) continue;
            float4 hv = *(const float4*)(sC + r * CLD + lane * 4);
            float s1 = hv.x * as.x + hv.y * as.y + hv.z * as.z + hv.w * as.w;
            float s2 = hv.x * ad.x + hv.y * ad.y + hv.z * ad.z + hv.w * ad.w;
            s1 = warp_sum(s1);
            s2 = warp_sum(s2);
            float al = s1 + s2;
            al = al > 0.f ? al : 0.2f * al;
            float el = expf(al);
            if (lane == 0) {
                g_asrc[gr] = s1;
                g_adst[gr] = s2;
                g_denom[gr] = el;
            }
            ((float4*)(g_h + (size_t)gr * DD))[lane] = hv;
            float4 o = make_float4(hv.x * el, hv.y * el, hv.z * el, hv.w * el);
            ((float4*)(g_acc + (size_t)gr * DD))[lane] = o;
        }
    } else {  // mode 4
        float4 bb = ((const float4*)bias)[lane];
        float4 gm = ((const float4*)q1)[lane];
        float4 bt = ((const float4*)q2)[lane];
        #pragma unroll
        for (int rr = 0; rr < 8; rr++) {
            int r = wid * 8 + rr;
            int gr = row0 + r;
            if (gr >= M) continue;
            float4 v = *(const float4*)(sC + r * CLD + lane * 4);
            float4 rv = ((const float4*)(resid + (size_t)gr * DD))[lane];
            v.x += bb.x + rv.x; v.y += bb.y + rv.y;
            v.z += bb.z + rv.z; v.w += bb.w + rv.w;
            float s1 = v.x + v.y + v.z + v.w;
            float s2 = v.x * v.x + v.y * v.y + v.z * v.z + v.w * v.w;
            s1 = warp_sum(s1);
            s2 = warp_sum(s2);
            float mean = s1 * (1.f / DD);
            float var = s2 * (1.f / DD) - mean * mean;
            float rs = rsqrtf(var + 1e-5f);
            float4 o = make_float4((v.x - mean) * rs * gm.x + bt.x,
                                   (v.y - mean) * rs * gm.y + bt.y,
                                   (v.z - mean) * rs * gm.z + bt.z,
                                   (v.w - mean) * rs * gm.w + bt.w);
            ((float4*)(Cf + (size_t)gr * DD))[lane] = o;
        }
    }
}

// ---------------- fused edge kernel: softmax weight + aggregate ------------------
__global__ void k_edge(const void* __restrict__ ei, int E) {
    int w = blockIdx.x * (blockDim.x >> 5) + (threadIdx.x >> 5);
    int lane = threadIdx.x & 31;
    int e0 = w * 2, e1 = e0 + 1;
    if (e0 >= E) return;
    bool has1 = (e1 < E);

    int s0, d0, s1 = 0, d1 = 0;
    load_edge(ei, e0, E, s0, d0);
    if (has1) load_edge(ei, e1, E, s1, d1);

    float as0 = g_asrc[s0], ad0 = g_adst[d0];
    float as1 = has1 ? g_asrc[s1] : 0.f, ad1 = has1 ? g_adst[d1] : 0.f;

    const float4* hp0 = (const float4*)(g_h + (size_t)s0 * DD);
    const float4* hp1 = (const float4*)(g_h + (size_t)s1 * DD);
    float4 h0 = hp0[lane];
    float4 h1 = has1 ? hp1[lane] : make_float4(0.f, 0.f, 0.f, 0.f);

    float al0 = as0 + ad0; al0 = al0 > 0.f ? al0 : 0.2f * al0;
    float ex0 = expf(al0);
    float al1 = as1 + ad1; al1 = al1 > 0.f ? al1 : 0.2f * al1;
    float ex1 = expf(al1);

    if (lane == 0) {
        atomicAdd(&g_denom[d0], ex0);
        if (has1) atomicAdd(&g_denom[d1], ex1);
    }
    red_add_v4(g_acc + (size_t)d0 * DD + lane * 4,
               make_float4(h0.x * ex0, h0.y * ex0, h0.z * ex0, h0.w * ex0));
    if (has1)
        red_add_v4(g_acc + (size_t)d1 * DD + lane * 4,
                   make_float4(h1.x * ex1, h1.y * ex1, h1.z * ex1, h1.w * ex1));
}

// ---------------- fused normalize + bias + residual + LayerNorm1 -> v1 ----------
__global__ void k_ln1(const float* __restrict__ x, const float* __restrict__ gbias,
                      const float* __restrict__ gam, const float* __restrict__ bet, int n) {
    int w = (blockIdx.x * blockDim.x + threadIdx.x) >> 5;
    int lane = threadIdx.x & 31;
    if (w >= n) return;
    float inv = 1.f / (g_denom[w] + 1e-16f);
    float4 a = ((const float4*)(g_acc + (size_t)w * DD))[lane];
    float4 gb = ((const float4*)gbias)[lane];
    float4 xv = ((const float4*)(x + (size_t)w * DD))[lane];
    float4 p = make_float4(a.x * inv + gb.x + xv.x, a.y * inv + gb.y + xv.y,
                           a.z * inv + gb.z + xv.z, a.w * inv + gb.w + xv.w);
    float s1 = p.x + p.y + p.z + p.w;
    float s2 = p.x * p.x + p.y * p.y + p.z * p.z + p.w * p.w;
    s1 = warp_sum(s1);
    s2 = warp_sum(s2);
    float mean = s1 * (1.f / DD);
    float var = s2 * (1.f / DD) - mean * mean;
    float rs = rsqrtf(var + 1e-5f);
    float4 gm = ((const float4*)gam)[lane];
    float4 bt = ((const float4*)bet)[lane];
    float4 o = make_float4((p.x - mean) * rs * gm.x + bt.x,
                           (p.y - mean) * rs * gm.y + bt.y,
                           (p.z - mean) * rs * gm.z + bt.z,
                           (p.w - mean) * rs * gm.w + bt.w);
    ((float4*)(g_v1 + (size_t)w * DD))[lane] = o;
}

// ---------------- launch ----------------
extern "C" void kernel_launch(void* const* d_in, const int* in_sizes, int n_in,
                              void* d_out, int out_size) {
    const float* x        = (const float*)d_in[0];
    const void*  ei       = d_in[1];
    // d_in[2] = edge_attr (ignored; GATConv built with edge_dim=None)
    const float* W        = (const float*)d_in[3];
    const float* att_src  = (const float*)d_in[4];
    const float* att_dst  = (const float*)d_in[5];
    const float* gat_bias = (const float*)d_in[6];
    const float* W1       = (const float*)d_in[7];
    const float* b1       = (const float*)d_in[8];
    const float* W2       = (const float*)d_in[9];
    const float* b2       = (const float*)d_in[10];
    const float* ln1_g    = (const float*)d_in[11];
    const float* ln1_b    = (const float*)d_in[12];
    const float* ln2_g    = (const float*)d_in[13];
    const float* ln2_b    = (const float*)d_in[14];
    float* out = (float*)d_out;

    const int n = in_sizes[0] / DD;
    const int E = in_sizes[1] / 2;
    const int mtiles = (n + 127) / 128;

    float *pv1, *pt;
    __nv_bfloat16 *pw0h, *pw0l, *pw1h, *pw1l, *pw2h, *pw2l;
    cudaGetSymbolAddress((void**)&pv1,  g_v1);
    cudaGetSymbolAddress((void**)&pt,   g_t);
    cudaGetSymbolAddress((void**)&pw0h, g_wt0h);
    cudaGetSymbolAddress((void**)&pw0l, g_wt0l);
    cudaGetSymbolAddress((void**)&pw1h, g_wt1h);
    cudaGetSymbolAddress((void**)&pw1l, g_wt1l);
    cudaGetSymbolAddress((void**)&pw2h, g_wt2h);
    cudaGetSymbolAddress((void**)&pw2l, g_wt2l);

    cudaFuncSetAttribute(k_wgemm, cudaFuncAttributeMaxDynamicSharedMemorySize, WG_SMEM);

    // 0. weight prep A (W, W1) + idx32 reset
    k_prep_a<<<(DD * DD + DD * FFD + 255) / 256, 256>>>(W, W1);

    // 1. weight prep B (W2)
    k_prep_b<<<(FFD * DD + 255) / 256, 256>>>(W2);

    // 2. edge_index dtype detection (int32 vs int64)
    k_detect<<<512, 256>>>((const unsigned int*)ei, E);

    // 3. h = x @ W  (HMMA) + fused node init   (profiled slot)
    {
        dim3 grid(mtiles, 1);
        k_wgemm<<<grid, 512, WG_SMEM>>>(x, pw0h, pw0l, nullptr, nullptr, nullptr,
                                        att_src, att_dst, n, DD, DD, 3);
    }

    // 4. fused edge softmax-weight + aggregation
    k_edge<<<(E + 15) / 16, 256>>>(ei, E);

    // 5. normalize + gat_bias + residual + LN1 -> v1
    k_ln1<<<(n * 32 + 255) / 256, 256>>>(x, gat_bias, ln1_g, ln1_b, n);

    // 6. t = relu(v1 @ W1 + b1)  (HMMA)
    {
        dim3 grid(mtiles, FFD / 128);
        k_wgemm<<<grid, 512, WG_SMEM>>>(pv1, pw1h, pw1l, pt, b1, nullptr,
                                        nullptr, nullptr, n, DD, FFD, 1);
    }

    // 7. out = LN2(t @ W2 + b2 + v1)  (HMMA, fused LN epilogue)
    {
        dim3 grid(mtiles, 1);
        k_wgemm<<<grid, 512, WG_SMEM>>>(pt, pw2h, pw2l, out, b2, pv1,
                                        ln2_g, ln2_b, n, FFD, DD, 4);
    }
}

// round 12
// speedup vs baseline: 1.4653x; 1.4653x over previous
#include <cuda_runtime.h>
#include <cuda_bf16.h>
#include <mma.h>
#include <cstdint>

using namespace nvcuda;

#define NN 50000
#define EE 800000
#define DD 128
#define FFD 512

// ---------------- scratch (static device globals; no allocs allowed) -------------
__device__ __align__(16) __nv_bfloat16 g_hb[NN * DD];   // h = x @ W (bf16, edge gather)
__device__ __align__(16) float g_acc[NN * DD];          // unnormalized aggregation
__device__ __align__(16) float g_v1 [NN * DD];          // LN1 output (residual for LN2)
__device__ __align__(16) __nv_bfloat16 g_th[NN * FFD];  // relu(v1@W1+b1) hi
__device__ __align__(16) __nv_bfloat16 g_tl[NN * FFD];  // relu(v1@W1+b1) lo
__device__ float g_asrc[NN];
__device__ float g_adst[NN];
__device__ float g_denom[NN];
__device__ int   g_idx32;   // 1 if edge_index is int32, 0 if int64

// weights, transposed to [N,K] K-major, bf16 hi/lo split
__device__ __align__(16) __nv_bfloat16 g_wt0h[DD * DD];
__device__ __align__(16) __nv_bfloat16 g_wt0l[DD * DD];
__device__ __align__(16) __nv_bfloat16 g_wt1h[FFD * DD];
__device__ __align__(16) __nv_bfloat16 g_wt1l[FFD * DD];
__device__ __align__(16) __nv_bfloat16 g_wt2h[DD * FFD];
__device__ __align__(16) __nv_bfloat16 g_wt2l[DD * FFD];

// ---------------- small helpers ----------------
__device__ __forceinline__ uint32_t smem_u32(const void* p) {
    uint32_t a;
    asm("{ .reg .u64 t; cvta.to.shared.u64 t, %1; cvt.u32.u64 %0, t; }" : "=r"(a) : "l"(p));
    return a;
}

__device__ __forceinline__ void cp_async16(uint32_t saddr, const void* gaddr) {
    asm volatile("cp.async.cg.shared.global [%0], [%1], 16;" :: "r"(saddr), "l"(gaddr));
}
#define CP_COMMIT() asm volatile("cp.async.commit_group;" ::: "memory")
#define CP_WAIT0()  asm volatile("cp.async.wait_group 0;" ::: "memory")

__device__ __forceinline__ void load_edge(const void* ei, int e, int E, int& s, int& d) {
    if (g_idx32) {
        const int* p = (const int*)ei;
        s = p[e]; d = p[E + e];
    } else {
        const long long* p = (const long long*)ei;
        s = (int)p[e]; d = (int)p[(size_t)E + e];
    }
}

__device__ __forceinline__ void red_add_v4(float* addr, float4 v) {
    asm volatile("red.global.add.v4.f32 [%0], {%1,%2,%3,%4};"
                 :: "l"(addr), "f"(v.x), "f"(v.y), "f"(v.z), "f"(v.w) : "memory");
}

__device__ __forceinline__ float warp_sum(float v) {
    #pragma unroll
    for (int o = 16; o > 0; o >>= 1) v += __shfl_xor_sync(0xffffffffu, v, o);
    return v;
}

__device__ __forceinline__ void split1(float v, __nv_bfloat16& h, __nv_bfloat16& l) {
    h = __float2bfloat16(v);
    l = __float2bfloat16(v - __bfloat162float(h));
}

// ---------------- prep A: W, W1 transpose+split + idx32 reset -------------------
__global__ void k_prep_a(const float* __restrict__ W, const float* __restrict__ W1) {
    int idx = blockIdx.x * blockDim.x + threadIdx.x;
    if (idx == 0) g_idx32 = 0;
    __nv_bfloat16 h, l;
    if (idx < DD * DD) {
        int k = idx / DD, n = idx % DD;
        split1(W[idx], h, l);
        g_wt0h[n * DD + k] = h;
        g_wt0l[n * DD + k] = l;
    } else if (idx < DD * DD + DD * FFD) {
        int i = idx - DD * DD;
        int k = i / FFD, n = i % FFD;
        split1(W1[i], h, l);
        g_wt1h[n * DD + k] = h;
        g_wt1l[n * DD + k] = l;
    }
}

// ---------------- prep B: W2 transpose+split ------------------------------------
__global__ void k_prep_b(const float* __restrict__ W2) {
    int idx = blockIdx.x * blockDim.x + threadIdx.x;
    if (idx < FFD * DD) {
        int k = idx / DD, n = idx % DD;
        __nv_bfloat16 h, l;
        split1(W2[idx], h, l);
        g_wt2h[n * FFD + k] = h;
        g_wt2l[n * FFD + k] = l;
    }
}

// ---------------- dtype detection ----------------
__global__ void k_detect(const unsigned int* w, int E) {
    int any = 0;
    for (int i = blockIdx.x * blockDim.x + threadIdx.x; i < E; i += gridDim.x * blockDim.x)
        if (w[2 * i + 1] != 0u) any = 1;
    if (any) g_idx32 = 1;
}

// ---------------- wmma (HMMA) bf16-split GEMM, 512 threads / 16 warps ------------
// C[M,Nn] = A[M,K] @ Bt[Nn,K]^T with 3-term hi/lo compensation.
// A: fp32 (Af, register-split) OR pre-split bf16 (Ahb/Alb, pure cp.async).
// CTA tile 128x128, 16 warps as 4x4, warp tile 32x32. SLDA=48 (measured best).
// mode 1: Ch/Cl = split(relu(r + bias))                 (t, bf16 hi/lo)
// mode 3: Ch = bf16(h rows) + fused node init
// mode 4: Cf = LN(r + bias + resid; q1=gamma, q2=beta)  (final out)
#define SLDA 48
#define CLD  132
#define AH_OFF 0
#define AL_OFF (128 * SLDA * 2)              // 12288
#define BH_OFF (2 * 128 * SLDA * 2)          // 24576
#define BL_OFF (3 * 128 * SLDA * 2)          // 36864
#define STAGE  (4 * 128 * SLDA * 2)          // 49152
#define WG_SMEM (2 * STAGE)                  // 98304 (>= 128*CLD*4 for C stage)

__global__ void __launch_bounds__(512)
k_wgemm(const float* __restrict__ Af,
        const __nv_bfloat16* __restrict__ Ahb, const __nv_bfloat16* __restrict__ Alb,
        const __nv_bfloat16* __restrict__ Bh, const __nv_bfloat16* __restrict__ Bl,
        float* __restrict__ Cf, __nv_bfloat16* __restrict__ Ch, __nv_bfloat16* __restrict__ Cl,
        const float* __restrict__ bias, const float* __restrict__ resid,
        const float* __restrict__ q1, const float* __restrict__ q2,
        int M, int K, int Nn, int mode) {
    extern __shared__ char smem[];
    const int tid = threadIdx.x;
    const int wid = tid >> 5;
    const int lane = tid & 31;
    const int warp_m = wid & 3;          // 4 m-groups of 32 rows
    const int warp_n = wid >> 2;         // 4 n-groups of 32 cols
    const int row0 = blockIdx.x * 128;
    const int col0 = blockIdx.y * 128;
    uint32_t sbase = smem_u32(smem);
    const bool a_pre = (Ahb != nullptr);

    // fill coords: 512 threads cover 128 rows x 4 chunks (8 elems each) exactly
    const int fr = tid >> 2, fq = tid & 3;
    int ga = row0 + fr; if (ga > M - 1) ga = M - 1;

    wmma::fragment<wmma::accumulator, 16, 16, 16, float> acc[2][2];
    #pragma unroll
    for (int i = 0; i < 2; i++)
        #pragma unroll
        for (int j = 0; j < 2; j++) wmma::fill_fragment(acc[i][j], 0.f);

    float4 pa[2];

    #define FILL_B(kk, stg) do {                                              \
        uint32_t so = sbase + (stg) * STAGE + BH_OFF + fr * (SLDA*2) + fq*16;  \
        size_t bo = (size_t)(col0 + fr) * K + (kk) + fq * 8;                  \
        cp_async16(so, Bh + bo);                                              \
        cp_async16(so + (BL_OFF - BH_OFF), Bl + bo);                          \
    } while (0)

    // A pre-split bf16: pure cp.async
    #define FILL_A_BF(kk, stg) do {                                           \
        uint32_t so = sbase + (stg) * STAGE + AH_OFF + fr * (SLDA*2) + fq*16;  \
        size_t ao = (size_t)ga * K + (kk) + fq * 8;                           \
        cp_async16(so, Ahb + ao);                                             \
        cp_async16(so + (AL_OFF - AH_OFF), Alb + ao);                         \
    } while (0)

    #define LOAD_A(kk) do {                                                   \
        const float* p = Af + (size_t)ga * K + (kk) + fq * 8;                 \
        pa[0] = *(const float4*)p; pa[1] = *(const float4*)(p + 4);           \
    } while (0)

    #define STORE_A(stg) do {                                                 \
        float f[8] = {pa[0].x, pa[0].y, pa[0].z, pa[0].w,                     \
                      pa[1].x, pa[1].y, pa[1].z, pa[1].w};                    \
        __nv_bfloat162 vh[4], vl[4];                                          \
        _Pragma("unroll")                                                     \
        for (int j = 0; j < 4; j++) {                                         \
            __nv_bfloat16 h0, l0, h1, l1;                                     \
            split1(f[2*j], h0, l0); split1(f[2*j+1], h1, l1);                 \
            vh[j] = __nv_bfloat162(h0, h1); vl[j] = __nv_bfloat162(l0, l1);   \
        }                                                                     \
        char* ba = smem + (stg) * STAGE + fr * (SLDA*2) + fq * 16;            \
        *(uint4*)(ba + AH_OFF) = *(uint4*)vh;                                 \
        *(uint4*)(ba + AL_OFF) = *(uint4*)vl;                                 \
    } while (0)

    // prologue
    if (a_pre) {
        FILL_A_BF(0, 0);
        FILL_B(0, 0);
        CP_COMMIT();
    } else {
        LOAD_A(0);
        FILL_B(0, 0);
        CP_COMMIT();
        STORE_A(0);
    }
    CP_WAIT0();
    __syncthreads();

    int stg = 0;
    for (int kk = 0; kk < K; kk += 32) {
        bool more = (kk + 32 < K);
        if (more) {
            if (a_pre) {
                FILL_A_BF(kk + 32, stg ^ 1);
                FILL_B(kk + 32, stg ^ 1);
                CP_COMMIT();
            } else {
                FILL_B(kk + 32, stg ^ 1);
                CP_COMMIT();
                LOAD_A(kk + 32);
            }
        }

        const __nv_bfloat16* sAh = (const __nv_bfloat16*)(smem + stg * STAGE + AH_OFF);
        const __nv_bfloat16* sBh = (const __nv_bfloat16*)(smem + stg * STAGE + BH_OFF);

        #pragma unroll
        for (int ks = 0; ks < 32; ks += 16) {
            wmma::fragment<wmma::matrix_a, 16, 16, 16, __nv_bfloat16, wmma::row_major> ah[2], al[2];
            wmma::fragment<wmma::matrix_b, 16, 16, 16, __nv_bfloat16, wmma::col_major> bh[2], bl[2];
            #pragma unroll
            for (int i = 0; i < 2; i++) {
                const __nv_bfloat16* pA = sAh + (warp_m * 32 + i * 16) * SLDA + ks;
                wmma::load_matrix_sync(ah[i], pA, SLDA);
                wmma::load_matrix_sync(al[i], pA + (AL_OFF - AH_OFF) / 2, SLDA);
            }
            #pragma unroll
            for (int j = 0; j < 2; j++) {
                const __nv_bfloat16* pB = sBh + (warp_n * 32 + j * 16) * SLDA + ks;
                wmma::load_matrix_sync(bh[j], pB, SLDA);
                wmma::load_matrix_sync(bl[j], pB + (BL_OFF - BH_OFF) / 2, SLDA);
            }
            // term-outer issue order: consecutive MMAs hit different accumulators
            #pragma unroll
            for (int i = 0; i < 2; i++)
                #pragma unroll
                for (int j = 0; j < 2; j++)
                    wmma::mma_sync(acc[i][j], ah[i], bh[j], acc[i][j]);
            #pragma unroll
            for (int i = 0; i < 2; i++)
                #pragma unroll
                for (int j = 0; j < 2; j++)
                    wmma::mma_sync(acc[i][j], ah[i], bl[j], acc[i][j]);
            #pragma unroll
            for (int i = 0; i < 2; i++)
                #pragma unroll
                for (int j = 0; j < 2; j++)
                    wmma::mma_sync(acc[i][j], al[i], bh[j], acc[i][j]);
        }

        if (more) {
            if (!a_pre) STORE_A(stg ^ 1);
            CP_WAIT0();
        }
        __syncthreads();
        stg ^= 1;
    }

    // stage C tile in smem
    float* sC = (float*)smem;
    #pragma unroll
    for (int i = 0; i < 2; i++)
        #pragma unroll
        for (int j = 0; j < 2; j++)
            wmma::store_matrix_sync(sC + (warp_m * 32 + i * 16) * CLD + warp_n * 32 + j * 16,
                                    acc[i][j], CLD, wmma::mem_row_major);
    __syncthreads();

    if (mode == 1) {
        // t = split(relu(r + bias)) -> bf16 hi/lo
        #pragma unroll
        for (int it = 0; it < 8; it++) {
            int i = tid + it * 512;
            int rr = i >> 5, q = i & 31;
            int gr = row0 + rr;
            if (gr >= M) continue;
            int gc = col0 + q * 4;
            float4 v = *(const float4*)(sC + rr * CLD + q * 4);
            const float4 bb = *(const float4*)(bias + gc);
            v.x = fmaxf(v.x + bb.x, 0.f); v.y = fmaxf(v.y + bb.y, 0.f);
            v.z = fmaxf(v.z + bb.z, 0.f); v.w = fmaxf(v.w + bb.w, 0.f);
            __nv_bfloat16 h0, h1, h2, h3, l0, l1, l2, l3;
            split1(v.x, h0, l0); split1(v.y, h1, l1);
            split1(v.z, h2, l2); split1(v.w, h3, l3);
            size_t ob = (size_t)gr * Nn + gc;
            *(__nv_bfloat162*)(Ch + ob)     = __nv_bfloat162(h0, h1);
            *(__nv_bfloat162*)(Ch + ob + 2) = __nv_bfloat162(h2, h3);
            *(__nv_bfloat162*)(Cl + ob)     = __nv_bfloat162(l0, l1);
            *(__nv_bfloat162*)(Cl + ob + 2) = __nv_bfloat162(l2, l3);
        }
    } else if (mode == 3) {
        // bf16 h rows + fused node init: warp per row, 8 rows per warp
        float4 as = ((const float4*)q1)[lane];
        float4 ad = ((const float4*)q2)[lane];
        #pragma unroll
        for (int rr = 0; rr < 8; rr++) {
            int r = wid * 8 + rr;
            int gr = row0 + r;
            if (gr >= M) continue;
            float4 hv = *(const float4*)(sC + r * CLD + lane * 4);
            float s1 = hv.x * as.x + hv.y * as.y + hv.z * as.z + hv.w * as.w;
            float s2 = hv.x * ad.x + hv.y * ad.y + hv.z * ad.z + hv.w * ad.w;
            s1 = warp_sum(s1);
            s2 = warp_sum(s2);
            float al = s1 + s2;
            al = al > 0.f ? al : 0.2f * al;
            float el = expf(al);
            if (lane == 0) {
                g_asrc[gr] = s1;
                g_adst[gr] = s2;
                g_denom[gr] = el;
            }
            // bf16 h row for edge gather
            size_t hb = (size_t)gr * DD + lane * 4;
            *(__nv_bfloat162*)(Ch + hb) =
                __nv_bfloat162(__float2bfloat16(hv.x), __float2bfloat16(hv.y));
            *(__nv_bfloat162*)(Ch + hb + 2) =
                __nv_bfloat162(__float2bfloat16(hv.z), __float2bfloat16(hv.w));
            // fp32 self-loop init
            float4 o = make_float4(hv.x * el, hv.y * el, hv.z * el, hv.w * el);
            ((float4*)(g_acc + (size_t)gr * DD))[lane] = o;
        }
    } else {  // mode 4
        float4 bb = ((const float4*)bias)[lane];
        float4 gm = ((const float4*)q1)[lane];
        float4 bt = ((const float4*)q2)[lane];
        #pragma unroll
        for (int rr = 0; rr < 8; rr++) {
            int r = wid * 8 + rr;
            int gr = row0 + r;
            if (gr >= M) continue;
            float4 v = *(const float4*)(sC + r * CLD + lane * 4);
            float4 rv = ((const float4*)(resid + (size_t)gr * DD))[lane];
            v.x += bb.x + rv.x; v.y += bb.y + rv.y;
            v.z += bb.z + rv.z; v.w += bb.w + rv.w;
            float s1 = v.x + v.y + v.z + v.w;
            float s2 = v.x * v.x + v.y * v.y + v.z * v.z + v.w * v.w;
            s1 = warp_sum(s1);
            s2 = warp_sum(s2);
            float mean = s1 * (1.f / DD);
            float var = s2 * (1.f / DD) - mean * mean;
            float rs = rsqrtf(var + 1e-5f);
            float4 o = make_float4((v.x - mean) * rs * gm.x + bt.x,
                                   (v.y - mean) * rs * gm.y + bt.y,
                                   (v.z - mean) * rs * gm.z + bt.z,
                                   (v.w - mean) * rs * gm.w + bt.w);
            ((float4*)(Cf + (size_t)gr * DD))[lane] = o;
        }
    }
}

// ---------------- fused edge kernel: softmax weight + aggregate ------------------
// bf16 gather (256B/row), fp32 scatter. 2 edges per warp.
__global__ void k_edge(const void* __restrict__ ei, int E) {
    int w = blockIdx.x * (blockDim.x >> 5) + (threadIdx.x >> 5);
    int lane = threadIdx.x & 31;
    int e0 = w * 2, e1 = e0 + 1;
    if (e0 >= E) return;
    bool has1 = (e1 < E);

    int s0, d0, s1 = 0, d1 = 0;
    load_edge(ei, e0, E, s0, d0);
    if (has1) load_edge(ei, e1, E, s1, d1);

    float as0 = g_asrc[s0], ad0 = g_adst[d0];
    float as1 = has1 ? g_asrc[s1] : 0.f, ad1 = has1 ? g_adst[d1] : 0.f;

    const __nv_bfloat162* hp0 = (const __nv_bfloat162*)(g_hb + (size_t)s0 * DD);
    const __nv_bfloat162* hp1 = (const __nv_bfloat162*)(g_hb + (size_t)s1 * DD);
    __nv_bfloat162 a0 = hp0[lane * 2], b0 = hp0[lane * 2 + 1];
    __nv_bfloat162 a1, b1;
    if (has1) { a1 = hp1[lane * 2]; b1 = hp1[lane * 2 + 1]; }

    float al0 = as0 + ad0; al0 = al0 > 0.f ? al0 : 0.2f * al0;
    float ex0 = expf(al0);
    float al1 = as1 + ad1; al1 = al1 > 0.f ? al1 : 0.2f * al1;
    float ex1 = expf(al1);

    if (lane == 0) {
        atomicAdd(&g_denom[d0], ex0);
        if (has1) atomicAdd(&g_denom[d1], ex1);
    }
    float2 a0f = __bfloat1622float2(a0), b0f = __bfloat1622float2(b0);
    red_add_v4(g_acc + (size_t)d0 * DD + lane * 4,
               make_float4(a0f.x * ex0, a0f.y * ex0, b0f.x * ex0, b0f.y * ex0));
    if (has1) {
        float2 a1f = __bfloat1622float2(a1), b1f = __bfloat1622float2(b1);
        red_add_v4(g_acc + (size_t)d1 * DD + lane * 4,
                   make_float4(a1f.x * ex1, a1f.y * ex1, b1f.x * ex1, b1f.y * ex1));
    }
}

// ---------------- fused normalize + bias + residual + LayerNorm1 -> v1 ----------
__global__ void k_ln1(const float* __restrict__ x, const float* __restrict__ gbias,
                      const float* __restrict__ gam, const float* __restrict__ bet, int n) {
    int w = (blockIdx.x * blockDim.x + threadIdx.x) >> 5;
    int lane = threadIdx.x & 31;
    if (w >= n) return;
    float inv = 1.f / (g_denom[w] + 1e-16f);
    float4 a = ((const float4*)(g_acc + (size_t)w * DD))[lane];
    float4 gb = ((const float4*)gbias)[lane];
    float4 xv = ((const float4*)(x + (size_t)w * DD))[lane];
    float4 p = make_float4(a.x * inv + gb.x + xv.x, a.y * inv + gb.y + xv.y,
                           a.z * inv + gb.z + xv.z, a.w * inv + gb.w + xv.w);
    float s1 = p.x + p.y + p.z + p.w;
    float s2 = p.x * p.x + p.y * p.y + p.z * p.z + p.w * p.w;
    s1 = warp_sum(s1);
    s2 = warp_sum(s2);
    float mean = s1 * (1.f / DD);
    float var = s2 * (1.f / DD) - mean * mean;
    float rs = rsqrtf(var + 1e-5f);
    float4 gm = ((const float4*)gam)[lane];
    float4 bt = ((const float4*)bet)[lane];
    float4 o = make_float4((p.x - mean) * rs * gm.x + bt.x,
                           (p.y - mean) * rs * gm.y + bt.y,
                           (p.z - mean) * rs * gm.z + bt.z,
                           (p.w - mean) * rs * gm.w + bt.w);
    ((float4*)(g_v1 + (size_t)w * DD))[lane] = o;
}

// ---------------- launch ----------------
extern "C" void kernel_launch(void* const* d_in, const int* in_sizes, int n_in,
                              void* d_out, int out_size) {
    const float* x        = (const float*)d_in[0];
    const void*  ei       = d_in[1];
    // d_in[2] = edge_attr (ignored; GATConv built with edge_dim=None)
    const float* W        = (const float*)d_in[3];
    const float* att_src  = (const float*)d_in[4];
    const float* att_dst  = (const float*)d_in[5];
    const float* gat_bias = (const float*)d_in[6];
    const float* W1       = (const float*)d_in[7];
    const float* b1       = (const float*)d_in[8];
    const float* W2       = (const float*)d_in[9];
    const float* b2       = (const float*)d_in[10];
    const float* ln1_g    = (const float*)d_in[11];
    const float* ln1_b    = (const float*)d_in[12];
    const float* ln2_g    = (const float*)d_in[13];
    const float* ln2_b    = (const float*)d_in[14];
    float* out = (float*)d_out;

    const int n = in_sizes[0] / DD;
    const int E = in_sizes[1] / 2;
    const int mtiles = (n + 127) / 128;

    float *pv1;
    __nv_bfloat16 *phb, *pth, *ptl;
    __nv_bfloat16 *pw0h, *pw0l, *pw1h, *pw1l, *pw2h, *pw2l;
    cudaGetSymbolAddress((void**)&pv1,  g_v1);
    cudaGetSymbolAddress((void**)&phb,  g_hb);
    cudaGetSymbolAddress((void**)&pth,  g_th);
    cudaGetSymbolAddress((void**)&ptl,  g_tl);
    cudaGetSymbolAddress((void**)&pw0h, g_wt0h);
    cudaGetSymbolAddress((void**)&pw0l, g_wt0l);
    cudaGetSymbolAddress((void**)&pw1h, g_wt1h);
    cudaGetSymbolAddress((void**)&pw1l, g_wt1l);
    cudaGetSymbolAddress((void**)&pw2h, g_wt2h);
    cudaGetSymbolAddress((void**)&pw2l, g_wt2l);

    cudaFuncSetAttribute(k_wgemm, cudaFuncAttributeMaxDynamicSharedMemorySize, WG_SMEM);

    // 0. weight prep A (W, W1) + idx32 reset
    k_prep_a<<<(DD * DD + DD * FFD + 255) / 256, 256>>>(W, W1);

    // 1. weight prep B (W2)
    k_prep_b<<<(FFD * DD + 255) / 256, 256>>>(W2);

    // 2. edge_index dtype detection (int32 vs int64)
    k_detect<<<512, 256>>>((const unsigned int*)ei, E);

    // 3. h = x @ W  (HMMA) -> bf16 h + fused node init   (profiled slot)
    {
        dim3 grid(mtiles, 1);
        k_wgemm<<<grid, 512, WG_SMEM>>>(x, nullptr, nullptr, pw0h, pw0l,
                                        nullptr, phb, nullptr, nullptr, nullptr,
                                        att_src, att_dst, n, DD, DD, 3);
    }

    // 4. fused edge softmax-weight + aggregation (bf16 gather)
    k_edge<<<(E + 15) / 16, 256>>>(ei, E);

    // 5. normalize + gat_bias + residual + LN1 -> v1
    k_ln1<<<(n * 32 + 255) / 256, 256>>>(x, gat_bias, ln1_g, ln1_b, n);

    // 6. t = relu(v1 @ W1 + b1)  (HMMA) -> bf16 hi/lo
    {
        dim3 grid(mtiles, FFD / 128);
        k_wgemm<<<grid, 512, WG_SMEM>>>(pv1, nullptr, nullptr, pw1h, pw1l,
                                        nullptr, pth, ptl, b1, nullptr,
                                        nullptr, nullptr, n, DD, FFD, 1);
    }

    // 7. out = LN2(t @ W2 + b2 + v1)  (HMMA, A pre-split, fused LN epilogue)
    {
        dim3 grid(mtiles, 1);
        k_wgemm<<<grid, 512, WG_SMEM>>>(nullptr, pth, ptl, pw2h, pw2l,
                                        out, nullptr, nullptr, b2, pv1,
                                        ln2_g, ln2_b, n, FFD, DD, 4);
    }
}